// round 10
// baseline (speedup 1.0000x reference)
#include <cuda_runtime.h>
#include <cuda_fp16.h>
#include <math.h>
#include <stdint.h>

#define BB 8
#define LL 4096
#define DD 1024
#define MM (BB * LL)          // 32768 rows
#define DD2 (2 * DD)          // 2048
#define NCH 32
#define CHUNK (LL / NCH)      // 128

// ---------------- scratch (device globals; no allocation allowed) ----------
__device__ float  g_avg[(size_t)MM * DD];      // cumulative mean (fp32)
__device__ float  g_avgout[(size_t)MM * DD];   // inter@w2+b2+avg (fp32)
__device__ __half g_h_h[(size_t)MM * DD];      // layernorm(avg), fp16
__device__ __half g_inter_h[(size_t)MM * DD];  // relu(h@w1+b1), fp16
__device__ __half g_avgout_h[(size_t)MM * DD]; // fp16 copy of avgout
__device__ __half g_in_h[(size_t)MM * DD];     // fp16 inputs
__device__ __half g_gates_h[(size_t)MM * DD2]; // concat@wg+bg, fp16
__device__ float  g_csum[BB * NCH * DD];       // chunk partial sums
__device__ __half g_w1t[DD * DD];              // w1^T [N][K], fp16
__device__ __half g_w2t[DD * DD];
__device__ __half g_wgt[(size_t)DD2 * DD2];

// ---------------- helpers ----------------------------------------------------
__device__ __forceinline__ float sigf(float x) { return 1.f / (1.f + __expf(-x)); }

#define CP_ASYNC16(dst, src) \
    asm volatile("cp.async.cg.shared.global [%0], [%1], 16;" \
                 :: "r"(dst), "l"(src) : "memory")
#define CP_COMMIT() asm volatile("cp.async.commit_group;" ::: "memory")

#define MMA_F16(c, a0, a1, a2, a3, b0, b1)                                    \
    asm volatile(                                                             \
        "mma.sync.aligned.m16n8k16.row.col.f32.f16.f16.f32 "                  \
        "{%0,%1,%2,%3}, {%4,%5,%6,%7}, {%8,%9}, {%0,%1,%2,%3};"               \
        : "+f"((c)[0]), "+f"((c)[1]), "+f"((c)[2]), "+f"((c)[3])              \
        : "r"(a0), "r"(a1), "r"(a2), "r"(a3), "r"(b0), "r"(b1))

#define LDSM_X4(r0, r1, r2, r3, addr)                                         \
    asm volatile("ldmatrix.sync.aligned.m8n8.x4.shared.b16 {%0,%1,%2,%3}, [%4];" \
                 : "=r"(r0), "=r"(r1), "=r"(r2), "=r"(r3) : "r"(addr))

// ---------------- phase 1: chunked cumulative sum --------------------------
__global__ void __launch_bounds__(256) k_chunksum(const float* __restrict__ in) {
    int idx = blockIdx.x * blockDim.x + threadIdx.x;
    int d = idx & (DD - 1);
    int chunk = (idx >> 10) & (NCH - 1);
    int b = idx >> 15;
    const float* p = in + ((size_t)(b * LL + chunk * CHUNK)) * DD + d;
    float s = 0.f;
#pragma unroll 4
    for (int l = 0; l < CHUNK; ++l) s += p[(size_t)l * DD];
    g_csum[(b * NCH + chunk) * DD + d] = s;
}

__global__ void __launch_bounds__(256) k_scan() {
    int idx = blockIdx.x * blockDim.x + threadIdx.x;
    int d = idx & (DD - 1);
    int b = idx >> 10;
    float run = 0.f;
#pragma unroll
    for (int c = 0; c < NCH; ++c) {
        int o = (b * NCH + c) * DD + d;
        float t = g_csum[o];
        g_csum[o] = run;
        run += t;
    }
}

__global__ void __launch_bounds__(256) k_apply(const float* __restrict__ in) {
    int idx = blockIdx.x * blockDim.x + threadIdx.x;
    int d = idx & (DD - 1);
    int chunk = (idx >> 10) & (NCH - 1);
    int b = idx >> 15;
    size_t base = ((size_t)(b * LL + chunk * CHUNK)) * DD + d;
    const float* p = in + base;
    float* q = g_avg + base;
    __half* qh = g_in_h + base;
    float run = g_csum[(b * NCH + chunk) * DD + d];
    int l0 = chunk * CHUNK;
#pragma unroll 4
    for (int l = 0; l < CHUNK; ++l) {
        float v = p[(size_t)l * DD];
        run += v;
        q[(size_t)l * DD] = run / (float)(l0 + l + 1);
        qh[(size_t)l * DD] = __float2half_rn(v);
    }
}

// ---------------- phase 2: layernorm over D per row (fp16 out) ---------------
__global__ void __launch_bounds__(256) k_ln(const float* __restrict__ lng,
                                            const float* __restrict__ lnb) {
    int row = blockIdx.x;
    int t = threadIdx.x;
    const float4* x4 = reinterpret_cast<const float4*>(g_avg + (size_t)row * DD);
    float4 a = x4[t];
    float s = a.x + a.y + a.z + a.w;
    float ss = a.x * a.x + a.y * a.y + a.z * a.z + a.w * a.w;
#pragma unroll
    for (int o = 16; o > 0; o >>= 1) {
        s  += __shfl_xor_sync(0xffffffffu, s, o);
        ss += __shfl_xor_sync(0xffffffffu, ss, o);
    }
    __shared__ float sm[16];
    int w = t >> 5;
    if ((t & 31) == 0) { sm[w] = s; sm[8 + w] = ss; }
    __syncthreads();
    if (t < 32) {
        float v1 = (t < 8) ? sm[t] : 0.f;
        float v2 = (t < 8) ? sm[8 + t] : 0.f;
#pragma unroll
        for (int o = 4; o > 0; o >>= 1) {
            v1 += __shfl_xor_sync(0xffffffffu, v1, o);
            v2 += __shfl_xor_sync(0xffffffffu, v2, o);
        }
        if (t == 0) { sm[0] = v1; sm[1] = v2; }
    }
    __syncthreads();
    float mean = sm[0] * (1.f / DD);
    float var  = sm[1] * (1.f / DD) - mean * mean;
    float inv  = rsqrtf(var + 1e-6f);
    float4 g = reinterpret_cast<const float4*>(lng)[t];
    float4 b = reinterpret_cast<const float4*>(lnb)[t];
    __half2 h0 = __floats2half2_rn((a.x - mean) * inv * g.x + b.x,
                                   (a.y - mean) * inv * g.y + b.y);
    __half2 h1 = __floats2half2_rn((a.z - mean) * inv * g.z + b.z,
                                   (a.w - mean) * inv * g.w + b.w);
    __half2* dst = reinterpret_cast<__half2*>(g_h_h + (size_t)row * DD);
    dst[t * 2 + 0] = h0;
    dst[t * 2 + 1] = h1;
}

// ---------------- weight transpose (fp16 out): Wt[n][k] = W[k][n] ------------
__global__ void __launch_bounds__(256) k_transpose(const float* __restrict__ W,
                                                   __half* __restrict__ Wt, int N) {
    __shared__ float t[32][33];
    int bx = blockIdx.x * 32, by = blockIdx.y * 32;
    int x = bx + threadIdx.x;
#pragma unroll
    for (int i = 0; i < 32; i += 8)
        t[threadIdx.y + i][threadIdx.x] = W[(size_t)(by + threadIdx.y + i) * N + x];
    __syncthreads();
    int x2 = by + threadIdx.x;
#pragma unroll
    for (int i = 0; i < 32; i += 8)
        Wt[(size_t)(bx + threadIdx.y + i) * N + x2] =
            __float2half_rn(t[threadIdx.x][threadIdx.y + i]);
}

// ---------------- phase 3: fp16 mma.sync GEMM, CTA 256x128 -------------------
// C[M,NN] = concatA[M,KTOT] @ Wt[NN,KTOT]^T (fp16 operands, fp32 accum).
// CTA tile 256x128 (25% less smem-fill traffic per MAC than 128x128),
// BK=64, 8 warps (4x2), warp tile 64x64, m16n8k16, ldmatrix.x4 fragments,
// 3-stage cp.async pipeline, single barrier per iter, 1 CTA/SM (256 regs/thr).
// MODE 0: relu(x+b) -> Ch   MODE 1: x+b+add -> Cf + fp16 Ch   MODE 2: x+b -> Ch
#define LDPH 72
#define A_TILE_H (256 * LDPH)             // halves
#define B_TILE_H (128 * LDPH)
#define STG_H (A_TILE_H + B_TILE_H)       // per stage
#define GEMM_SMEM (3 * STG_H * 2)         // 3 stages = 165888 B

template <int MODE, int KTOT, int NN>
__global__ void __launch_bounds__(256, 1) k_gemm_h(
    const __half* __restrict__ A0, const __half* __restrict__ A1,
    const __half* __restrict__ Wt, const float* __restrict__ bias,
    const float* __restrict__ add, float* __restrict__ Cf,
    __half* __restrict__ Ch) {
    extern __shared__ __half smh[];
    int tid = threadIdx.x;
    int wid = tid >> 5, lane = tid & 31;
    int g = lane >> 2, tg = lane & 3;
    int wm = wid >> 1, wn = wid & 1;       // 4 x 2 warp grid, 64x64 tiles
    int bm = blockIdx.y * 256, bn = blockIdx.x * 128;

    // per-lane ldmatrix offsets (in halves, within tile)
    int la_off = (lane & 15) * LDPH + (lane >> 4) * 8;                 // A x4
    int qb = lane >> 3;
    int lb_off = ((lane & 7) + (qb >> 1) * 8) * LDPH + (qb & 1) * 8;   // B x4

    float acc[32][4];                      // [mt*8+nt][4], mt<4, nt<8
#pragma unroll
    for (int i = 0; i < 32; ++i)
#pragma unroll
        for (int j = 0; j < 4; ++j) acc[i][j] = 0.f;

    const int NK = KTOT / 64;

#define LOAD_STAGE(s, kk_)                                                     \
    {                                                                          \
        int kk = (kk_);                                                        \
        const __half* Ab = A0; int kloc = kk;                                  \
        if (KTOT > DD && kk >= DD) { Ab = A1; kloc = kk - DD; }                \
        __half* As = smh + (s) * STG_H;                                        \
        __half* Bs = As + A_TILE_H;                                            \
        _Pragma("unroll")                                                      \
        for (int it = 0; it < 8; ++it) {                                       \
            int i = tid + it * 256;                                            \
            int r = i >> 3, c = (i & 7) << 3;                                  \
            uint32_t da = (uint32_t)__cvta_generic_to_shared(As + r * LDPH + c); \
            CP_ASYNC16(da, Ab + (size_t)(bm + r) * DD + kloc + c);             \
        }                                                                      \
        _Pragma("unroll")                                                      \
        for (int it = 0; it < 4; ++it) {                                       \
            int i = tid + it * 256;                                            \
            int r = i >> 3, c = (i & 7) << 3;                                  \
            uint32_t db = (uint32_t)__cvta_generic_to_shared(Bs + r * LDPH + c); \
            CP_ASYNC16(db, Wt + (size_t)(bn + r) * KTOT + kk + c);             \
        }                                                                      \
    }

    LOAD_STAGE(0, 0);
    CP_COMMIT();
    LOAD_STAGE(1, 64);
    CP_COMMIT();

    int cur = 0;
    for (int kt = 0; kt < NK; ++kt) {
        if (kt + 1 < NK) {
            asm volatile("cp.async.wait_group 1;" ::: "memory");
        } else {
            asm volatile("cp.async.wait_group 0;" ::: "memory");
        }
        __syncthreads();
        if (kt + 2 < NK) {
            int nxt = cur + 2; if (nxt >= 3) nxt -= 3;
            LOAD_STAGE(nxt, (kt + 2) * 64);
            CP_COMMIT();
        }

        const __half* As = smh + cur * STG_H;
        const __half* Bs = As + A_TILE_H;
        uint32_t aB = (uint32_t)__cvta_generic_to_shared(
            As + (size_t)(wm * 64) * LDPH + la_off);
        uint32_t bB = (uint32_t)__cvta_generic_to_shared(
            Bs + (size_t)(wn * 64) * LDPH + lb_off);
#pragma unroll
        for (int kc = 0; kc < 4; ++kc) {
            int kb2 = kc * 32;                       // byte offset of k16 chunk
            uint32_t af[4][4], bf[8][2];
#pragma unroll
            for (int mt = 0; mt < 4; ++mt)
                LDSM_X4(af[mt][0], af[mt][1], af[mt][2], af[mt][3],
                        aB + mt * (16 * LDPH * 2) + kb2);
#pragma unroll
            for (int p = 0; p < 4; ++p)
                LDSM_X4(bf[p * 2][0], bf[p * 2][1], bf[p * 2 + 1][0],
                        bf[p * 2 + 1][1], bB + p * (16 * LDPH * 2) + kb2);
#pragma unroll
            for (int mt = 0; mt < 4; ++mt)
#pragma unroll
                for (int nt = 0; nt < 8; ++nt)
                    MMA_F16(acc[mt * 8 + nt], af[mt][0], af[mt][1], af[mt][2],
                            af[mt][3], bf[nt][0], bf[nt][1]);
        }
        ++cur; if (cur >= 3) cur = 0;
    }

#pragma unroll
    for (int mt = 0; mt < 4; ++mt) {
#pragma unroll
        for (int nt = 0; nt < 8; ++nt) {
            float* c = acc[mt * 8 + nt];
            int col = bn + wn * 64 + nt * 8 + 2 * tg;
            float2 bb = *reinterpret_cast<const float2*>(bias + col);
#pragma unroll
            for (int hh = 0; hh < 2; ++hh) {
                int row = bm + wm * 64 + mt * 16 + g + hh * 8;
                size_t off = (size_t)row * NN + col;
                float vx = c[hh * 2 + 0] + bb.x;
                float vy = c[hh * 2 + 1] + bb.y;
                if (MODE == 0) {
                    *reinterpret_cast<__half2*>(Ch + off) =
                        __floats2half2_rn(fmaxf(vx, 0.f), fmaxf(vy, 0.f));
                } else if (MODE == 1) {
                    float2 ad = *reinterpret_cast<const float2*>(add + off);
                    vx += ad.x; vy += ad.y;
                    float2 o; o.x = vx; o.y = vy;
                    *reinterpret_cast<float2*>(Cf + off) = o;
                    *reinterpret_cast<__half2*>(Ch + off) = __floats2half2_rn(vx, vy);
                } else {
                    *reinterpret_cast<__half2*>(Ch + off) = __floats2half2_rn(vx, vy);
                }
            }
        }
    }
#undef LOAD_STAGE
}

// ---------------- phase 4: gate combine --------------------------------------
__global__ void __launch_bounds__(256) k_final(const float* __restrict__ in,
                                               float* __restrict__ out) {
    int idx = blockIdx.x * blockDim.x + threadIdx.x;   // over M*D/4
    int row = idx >> 8;                                 // D/4 = 256
    int d4 = idx & 255;
    float4 i4 = reinterpret_cast<const float4*>(in)[idx];
    float4 a4 = reinterpret_cast<const float4*>(g_avgout)[idx];
    const __half2* gr = reinterpret_cast<const __half2*>(
        g_gates_h + (size_t)row * DD2);
    __half2 g1a = gr[d4 * 2 + 0];
    __half2 g1b = gr[d4 * 2 + 1];
    __half2 g2a = gr[512 + d4 * 2 + 0];
    __half2 g2b = gr[512 + d4 * 2 + 1];
    float4 o;
    o.x = sigf(__low2float(g1a))  * i4.x + sigf(__low2float(g2a))  * a4.x;
    o.y = sigf(__high2float(g1a)) * i4.y + sigf(__high2float(g2a)) * a4.y;
    o.z = sigf(__low2float(g1b))  * i4.z + sigf(__low2float(g2b))  * a4.z;
    o.w = sigf(__high2float(g1b)) * i4.w + sigf(__high2float(g2b)) * a4.w;
    reinterpret_cast<float4*>(out)[idx] = o;
}

// ---------------- launch -----------------------------------------------------
extern "C" void kernel_launch(void* const* d_in, const int* in_sizes, int n_in,
                              void* d_out, int out_size) {
    const float* inputs = (const float*)d_in[0];
    const float* w1 = (const float*)d_in[1];
    const float* b1 = (const float*)d_in[2];
    const float* w2 = (const float*)d_in[3];
    const float* b2 = (const float*)d_in[4];
    const float* lng = (const float*)d_in[5];
    const float* lnb = (const float*)d_in[6];
    const float* wg = (const float*)d_in[7];
    const float* bg = (const float*)d_in[8];
    float* out = (float*)d_out;

    float *avg, *avgout;
    __half *hh, *interh, *avgouth, *inh, *gatesh, *w1t, *w2t, *wgt;
    cudaGetSymbolAddress((void**)&avg, g_avg);
    cudaGetSymbolAddress((void**)&avgout, g_avgout);
    cudaGetSymbolAddress((void**)&hh, g_h_h);
    cudaGetSymbolAddress((void**)&interh, g_inter_h);
    cudaGetSymbolAddress((void**)&avgouth, g_avgout_h);
    cudaGetSymbolAddress((void**)&inh, g_in_h);
    cudaGetSymbolAddress((void**)&gatesh, g_gates_h);
    cudaGetSymbolAddress((void**)&w1t, g_w1t);
    cudaGetSymbolAddress((void**)&w2t, g_w2t);
    cudaGetSymbolAddress((void**)&wgt, g_wgt);

    cudaFuncSetAttribute(k_gemm_h<0, DD, DD>,
                         cudaFuncAttributeMaxDynamicSharedMemorySize, GEMM_SMEM);
    cudaFuncSetAttribute(k_gemm_h<1, DD, DD>,
                         cudaFuncAttributeMaxDynamicSharedMemorySize, GEMM_SMEM);
    cudaFuncSetAttribute(k_gemm_h<2, DD2, DD2>,
                         cudaFuncAttributeMaxDynamicSharedMemorySize, GEMM_SMEM);

    dim3 tb(32, 8);
    k_transpose<<<dim3(DD / 32, DD / 32), tb>>>(w1, w1t, DD);
    k_transpose<<<dim3(DD / 32, DD / 32), tb>>>(w2, w2t, DD);
    k_transpose<<<dim3(DD2 / 32, DD2 / 32), tb>>>(wg, wgt, DD2);

    k_chunksum<<<(BB * NCH * DD) / 256, 256>>>(inputs);
    k_scan<<<(BB * DD) / 256, 256>>>();
    k_apply<<<(BB * NCH * DD) / 256, 256>>>(inputs);
    k_ln<<<MM, 256>>>(lng, lnb);

    dim3 grid12(DD / 128, MM / 256);     // (8, 128)
    k_gemm_h<0, DD, DD><<<grid12, 256, GEMM_SMEM>>>(hh, hh, w1t, b1, nullptr,
                                                    nullptr, interh);
    k_gemm_h<1, DD, DD><<<grid12, 256, GEMM_SMEM>>>(interh, interh, w2t, b2, avg,
                                                    avgout, avgouth);

    dim3 grid3(DD2 / 128, MM / 256);     // (16, 128)
    k_gemm_h<2, DD2, DD2><<<grid3, 256, GEMM_SMEM>>>(inh, avgouth, wgt, bg,
                                                     nullptr, nullptr, gatesh);

    k_final<<<((size_t)MM * DD / 4) / 256, 256>>>(inputs, out);
}

// round 12
// speedup vs baseline: 1.1096x; 1.1096x over previous
#include <cuda_runtime.h>
#include <cuda_fp16.h>
#include <math.h>
#include <stdint.h>
#include <string.h>

#define BB 8
#define LL 4096
#define DD 1024
#define MM (BB * LL)          // 32768 rows
#define DD2 (2 * DD)          // 2048
#define NCH 64
#define CHUNK (LL / NCH)      // 64

// ---------------- scratch (device globals; no allocation allowed) ----------
__device__ float  g_avg[(size_t)MM * DD];      // cumulative mean (fp32)
__device__ float  g_avgout[(size_t)MM * DD];   // inter@w2+b2+avg (fp32)
__device__ __half g_h_h[(size_t)MM * DD];      // layernorm(avg), fp16
__device__ __half g_inter_h[(size_t)MM * DD];  // relu(h@w1+b1), fp16
__device__ __half g_avgout_h[(size_t)MM * DD]; // fp16 copy of avgout
__device__ __half g_in_h[(size_t)MM * DD];     // fp16 inputs
__device__ __half g_gates_h[(size_t)MM * DD2]; // concat@wg+bg, fp16
__device__ float  g_csum[BB * NCH * DD];       // chunk partial sums
__device__ __half g_w1t[DD * DD];              // w1^T [N][K], fp16
__device__ __half g_w2t[DD * DD];
__device__ __half g_wgt[(size_t)DD2 * DD2];

// ---------------- helpers ----------------------------------------------------
__device__ __forceinline__ float sigf(float x) { return 1.f / (1.f + __expf(-x)); }

__device__ __forceinline__ uint32_t h2_bits(__half2 h) {
    uint32_t u;
    memcpy(&u, &h, 4);
    return u;
}

#define CP_ASYNC16(dst, src) \
    asm volatile("cp.async.cg.shared.global [%0], [%1], 16;" \
                 :: "r"(dst), "l"(src) : "memory")
#define CP_COMMIT() asm volatile("cp.async.commit_group;" ::: "memory")

#define MMA_F16(c, a0, a1, a2, a3, b0, b1)                                    \
    asm volatile(                                                             \
        "mma.sync.aligned.m16n8k16.row.col.f32.f16.f16.f32 "                  \
        "{%0,%1,%2,%3}, {%4,%5,%6,%7}, {%8,%9}, {%0,%1,%2,%3};"               \
        : "+f"((c)[0]), "+f"((c)[1]), "+f"((c)[2]), "+f"((c)[3])              \
        : "r"(a0), "r"(a1), "r"(a2), "r"(a3), "r"(b0), "r"(b1))

#define LDSM_X4(r0, r1, r2, r3, addr)                                         \
    asm volatile("ldmatrix.sync.aligned.m8n8.x4.shared.b16 {%0,%1,%2,%3}, [%4];" \
                 : "=r"(r0), "=r"(r1), "=r"(r2), "=r"(r3) : "r"(addr))

// ---------------- phase 1: chunked cumulative sum (float4 vectorized) --------
// idx over B*NCH*(D/4): d4 = idx & 255, chunk = (idx>>8) & 63, b = idx>>14.
__global__ void __launch_bounds__(256) k_chunksum(const float* __restrict__ in) {
    int idx = blockIdx.x * blockDim.x + threadIdx.x;   // 131072
    int d4 = idx & 255;
    int chunk = (idx >> 8) & (NCH - 1);
    int b = idx >> 14;
    const float4* p = reinterpret_cast<const float4*>(
        in + ((size_t)(b * LL + chunk * CHUNK)) * DD) + d4;
    float4 s = make_float4(0.f, 0.f, 0.f, 0.f);
#pragma unroll 4
    for (int l = 0; l < CHUNK; ++l) {
        float4 v = p[(size_t)l * 256];
        s.x += v.x; s.y += v.y; s.z += v.z; s.w += v.w;
    }
    reinterpret_cast<float4*>(g_csum + (b * NCH + chunk) * DD)[d4] = s;
}

__global__ void __launch_bounds__(256) k_scan() {
    int idx = blockIdx.x * blockDim.x + threadIdx.x;   // B*D/4 = 2048
    int d4 = idx & 255;
    int b = idx >> 8;
    float4 run = make_float4(0.f, 0.f, 0.f, 0.f);
#pragma unroll
    for (int c = 0; c < NCH; ++c) {
        float4* q = reinterpret_cast<float4*>(g_csum + (b * NCH + c) * DD) + d4;
        float4 t = *q;
        *q = run;                                       // exclusive
        run.x += t.x; run.y += t.y; run.z += t.z; run.w += t.w;
    }
}

__global__ void __launch_bounds__(256) k_apply(const float* __restrict__ in) {
    int idx = blockIdx.x * blockDim.x + threadIdx.x;   // 131072
    int d4 = idx & 255;
    int chunk = (idx >> 8) & (NCH - 1);
    int b = idx >> 14;
    size_t rowbase = (size_t)(b * LL + chunk * CHUNK) * DD;
    const float4* p = reinterpret_cast<const float4*>(in + rowbase) + d4;
    float4* q = reinterpret_cast<float4*>(g_avg + rowbase) + d4;
    uint2* qh = reinterpret_cast<uint2*>(g_in_h + rowbase) + d4;
    float4 run = reinterpret_cast<const float4*>(
        g_csum + (b * NCH + chunk) * DD)[d4];
    int l0 = chunk * CHUNK;
#pragma unroll 4
    for (int l = 0; l < CHUNK; ++l) {
        float4 v = p[(size_t)l * 256];
        run.x += v.x; run.y += v.y; run.z += v.z; run.w += v.w;
        float den = (float)(l0 + l + 1);
        float4 a;
        a.x = run.x / den; a.y = run.y / den;
        a.z = run.z / den; a.w = run.w / den;
        q[(size_t)l * 256] = a;
        uint2 hv;
        hv.x = h2_bits(__floats2half2_rn(v.x, v.y));
        hv.y = h2_bits(__floats2half2_rn(v.z, v.w));
        qh[(size_t)l * 256] = hv;
    }
}

// ---------------- phase 2: layernorm over D per row (fp16 out) ---------------
__global__ void __launch_bounds__(256) k_ln(const float* __restrict__ lng,
                                            const float* __restrict__ lnb) {
    int row = blockIdx.x;
    int t = threadIdx.x;
    const float4* x4 = reinterpret_cast<const float4*>(g_avg + (size_t)row * DD);
    float4 a = x4[t];
    float s = a.x + a.y + a.z + a.w;
    float ss = a.x * a.x + a.y * a.y + a.z * a.z + a.w * a.w;
#pragma unroll
    for (int o = 16; o > 0; o >>= 1) {
        s  += __shfl_xor_sync(0xffffffffu, s, o);
        ss += __shfl_xor_sync(0xffffffffu, ss, o);
    }
    __shared__ float sm[16];
    int w = t >> 5;
    if ((t & 31) == 0) { sm[w] = s; sm[8 + w] = ss; }
    __syncthreads();
    if (t < 32) {
        float v1 = (t < 8) ? sm[t] : 0.f;
        float v2 = (t < 8) ? sm[8 + t] : 0.f;
#pragma unroll
        for (int o = 4; o > 0; o >>= 1) {
            v1 += __shfl_xor_sync(0xffffffffu, v1, o);
            v2 += __shfl_xor_sync(0xffffffffu, v2, o);
        }
        if (t == 0) { sm[0] = v1; sm[1] = v2; }
    }
    __syncthreads();
    float mean = sm[0] * (1.f / DD);
    float var  = sm[1] * (1.f / DD) - mean * mean;
    float inv  = rsqrtf(var + 1e-6f);
    float4 g = reinterpret_cast<const float4*>(lng)[t];
    float4 b = reinterpret_cast<const float4*>(lnb)[t];
    __half2 h0 = __floats2half2_rn((a.x - mean) * inv * g.x + b.x,
                                   (a.y - mean) * inv * g.y + b.y);
    __half2 h1 = __floats2half2_rn((a.z - mean) * inv * g.z + b.z,
                                   (a.w - mean) * inv * g.w + b.w);
    __half2* dst = reinterpret_cast<__half2*>(g_h_h + (size_t)row * DD);
    dst[t * 2 + 0] = h0;
    dst[t * 2 + 1] = h1;
}

// ---------------- weight transpose (fp16 out): Wt[n][k] = W[k][n] ------------
__global__ void __launch_bounds__(256) k_transpose(const float* __restrict__ W,
                                                   __half* __restrict__ Wt, int N) {
    __shared__ float t[32][33];
    int bx = blockIdx.x * 32, by = blockIdx.y * 32;
    int x = bx + threadIdx.x;
#pragma unroll
    for (int i = 0; i < 32; i += 8)
        t[threadIdx.y + i][threadIdx.x] = W[(size_t)(by + threadIdx.y + i) * N + x];
    __syncthreads();
    int x2 = by + threadIdx.x;
#pragma unroll
    for (int i = 0; i < 32; i += 8)
        Wt[(size_t)(bx + threadIdx.y + i) * N + x2] =
            __float2half_rn(t[threadIdx.x][threadIdx.y + i]);
}

// ---------------- phase 3: fp16 mma.sync GEMM (R8 config, proven best) -------
// C[M,NN] = concatA[M,KTOT] @ Wt[NN,KTOT]^T (fp16 operands, fp32 accum).
// CTA tile 128x128, BK=64 halves, 8 warps (2x4), warp tile 64x32, m16n8k16.
// ldmatrix.x4 fragments; 3-stage cp.async pipeline, 1 barrier/iter, 2 CTAs/SM.
// MODE 0: relu(x+b) -> Ch   MODE 1: x+b+add -> Cf + fp16 Ch   MODE 2: x+b -> Ch
#define LDPH 72
#define TILE_H (128 * LDPH)               // halves per tile
#define STG_H (2 * TILE_H)                // A + B per stage
#define GEMM_SMEM (3 * STG_H * 2)         // 3 stages = 110592 B

template <int MODE, int KTOT, int NN>
__global__ void __launch_bounds__(256, 2) k_gemm_h(
    const __half* __restrict__ A0, const __half* __restrict__ A1,
    const __half* __restrict__ Wt, const float* __restrict__ bias,
    const float* __restrict__ add, float* __restrict__ Cf,
    __half* __restrict__ Ch) {
    extern __shared__ __half smh[];
    int tid = threadIdx.x;
    int wid = tid >> 5, lane = tid & 31;
    int g = lane >> 2, tg = lane & 3;
    int wm = wid >> 2, wn = wid & 3;       // 2 x 4 warp grid
    int bm = blockIdx.y * 128, bn = blockIdx.x * 128;

    // per-lane ldmatrix offsets (in halves, within tile)
    int la_off = (lane & 15) * LDPH + (lane >> 4) * 8;                 // A x4
    int qb = lane >> 3;
    int lb_off = ((lane & 7) + (qb >> 1) * 8) * LDPH + (qb & 1) * 8;   // B x4

    float acc[16][4];
#pragma unroll
    for (int i = 0; i < 16; ++i)
#pragma unroll
        for (int j = 0; j < 4; ++j) acc[i][j] = 0.f;

    const int NK = KTOT / 64;

#define LOAD_STAGE(s, kk_)                                                     \
    {                                                                          \
        int kk = (kk_);                                                        \
        const __half* Ab = A0; int kloc = kk;                                  \
        if (KTOT > DD && kk >= DD) { Ab = A1; kloc = kk - DD; }                \
        __half* As = smh + (s) * STG_H;                                        \
        __half* Bs = As + TILE_H;                                              \
        _Pragma("unroll")                                                      \
        for (int it = 0; it < 4; ++it) {                                       \
            int i = tid + it * 256;                                            \
            int r = i >> 3, c = (i & 7) << 3;                                  \
            uint32_t da = (uint32_t)__cvta_generic_to_shared(As + r * LDPH + c); \
            CP_ASYNC16(da, Ab + (size_t)(bm + r) * DD + kloc + c);             \
            uint32_t db = (uint32_t)__cvta_generic_to_shared(Bs + r * LDPH + c); \
            CP_ASYNC16(db, Wt + (size_t)(bn + r) * KTOT + kk + c);             \
        }                                                                      \
    }

    LOAD_STAGE(0, 0);
    CP_COMMIT();
    LOAD_STAGE(1, 64);
    CP_COMMIT();

    int cur = 0;
    for (int kt = 0; kt < NK; ++kt) {
        if (kt + 1 < NK) {
            asm volatile("cp.async.wait_group 1;" ::: "memory");
        } else {
            asm volatile("cp.async.wait_group 0;" ::: "memory");
        }
        __syncthreads();
        if (kt + 2 < NK) {
            int nxt = cur + 2; if (nxt >= 3) nxt -= 3;
            LOAD_STAGE(nxt, (kt + 2) * 64);
            CP_COMMIT();
        }

        const __half* As = smh + cur * STG_H;
        const __half* Bs = As + TILE_H;
        uint32_t aB = (uint32_t)__cvta_generic_to_shared(
            As + (size_t)(wm * 64) * LDPH + la_off);
        uint32_t bB = (uint32_t)__cvta_generic_to_shared(
            Bs + (size_t)(wn * 32) * LDPH + lb_off);
#pragma unroll
        for (int kc = 0; kc < 4; ++kc) {
            int kb2 = kc * 32;                       // byte offset of k16 chunk
            uint32_t af[4][4], bf[4][2];
#pragma unroll
            for (int mt = 0; mt < 4; ++mt)
                LDSM_X4(af[mt][0], af[mt][1], af[mt][2], af[mt][3],
                        aB + mt * (16 * LDPH * 2) + kb2);
#pragma unroll
            for (int p = 0; p < 2; ++p)
                LDSM_X4(bf[p * 2][0], bf[p * 2][1], bf[p * 2 + 1][0],
                        bf[p * 2 + 1][1], bB + p * (16 * LDPH * 2) + kb2);
#pragma unroll
            for (int mt = 0; mt < 4; ++mt)
#pragma unroll
                for (int nt = 0; nt < 4; ++nt)
                    MMA_F16(acc[mt * 4 + nt], af[mt][0], af[mt][1], af[mt][2],
                            af[mt][3], bf[nt][0], bf[nt][1]);
        }
        ++cur; if (cur >= 3) cur = 0;
    }

#pragma unroll
    for (int mt = 0; mt < 4; ++mt) {
#pragma unroll
        for (int nt = 0; nt < 4; ++nt) {
            float* c = acc[mt * 4 + nt];
            int col = bn + wn * 32 + nt * 8 + 2 * tg;
            float2 bb = *reinterpret_cast<const float2*>(bias + col);
#pragma unroll
            for (int hh = 0; hh < 2; ++hh) {
                int row = bm + wm * 64 + mt * 16 + g + hh * 8;
                size_t off = (size_t)row * NN + col;
                float vx = c[hh * 2 + 0] + bb.x;
                float vy = c[hh * 2 + 1] + bb.y;
                if (MODE == 0) {
                    *reinterpret_cast<__half2*>(Ch + off) =
                        __floats2half2_rn(fmaxf(vx, 0.f), fmaxf(vy, 0.f));
                } else if (MODE == 1) {
                    float2 ad = *reinterpret_cast<const float2*>(add + off);
                    vx += ad.x; vy += ad.y;
                    float2 o; o.x = vx; o.y = vy;
                    *reinterpret_cast<float2*>(Cf + off) = o;
                    *reinterpret_cast<__half2*>(Ch + off) = __floats2half2_rn(vx, vy);
                } else {
                    *reinterpret_cast<__half2*>(Ch + off) = __floats2half2_rn(vx, vy);
                }
            }
        }
    }
#undef LOAD_STAGE
}

// ---------------- phase 4: gate combine --------------------------------------
__global__ void __launch_bounds__(256) k_final(const float* __restrict__ in,
                                               float* __restrict__ out) {
    int idx = blockIdx.x * blockDim.x + threadIdx.x;   // over M*D/4
    int row = idx >> 8;                                 // D/4 = 256
    int d4 = idx & 255;
    float4 i4 = reinterpret_cast<const float4*>(in)[idx];
    float4 a4 = reinterpret_cast<const float4*>(g_avgout)[idx];
    const __half2* gr = reinterpret_cast<const __half2*>(
        g_gates_h + (size_t)row * DD2);
    __half2 g1a = gr[d4 * 2 + 0];
    __half2 g1b = gr[d4 * 2 + 1];
    __half2 g2a = gr[512 + d4 * 2 + 0];
    __half2 g2b = gr[512 + d4 * 2 + 1];
    float4 o;
    o.x = sigf(__low2float(g1a))  * i4.x + sigf(__low2float(g2a))  * a4.x;
    o.y = sigf(__high2float(g1a)) * i4.y + sigf(__high2float(g2a)) * a4.y;
    o.z = sigf(__low2float(g1b))  * i4.z + sigf(__low2float(g2b))  * a4.z;
    o.w = sigf(__high2float(g1b)) * i4.w + sigf(__high2float(g2b)) * a4.w;
    reinterpret_cast<float4*>(out)[idx] = o;
}

// ---------------- launch -----------------------------------------------------
extern "C" void kernel_launch(void* const* d_in, const int* in_sizes, int n_in,
                              void* d_out, int out_size) {
    const float* inputs = (const float*)d_in[0];
    const float* w1 = (const float*)d_in[1];
    const float* b1 = (const float*)d_in[2];
    const float* w2 = (const float*)d_in[3];
    const float* b2 = (const float*)d_in[4];
    const float* lng = (const float*)d_in[5];
    const float* lnb = (const float*)d_in[6];
    const float* wg = (const float*)d_in[7];
    const float* bg = (const float*)d_in[8];
    float* out = (float*)d_out;

    float *avg, *avgout;
    __half *hh, *interh, *avgouth, *inh, *gatesh, *w1t, *w2t, *wgt;
    cudaGetSymbolAddress((void**)&avg, g_avg);
    cudaGetSymbolAddress((void**)&avgout, g_avgout);
    cudaGetSymbolAddress((void**)&hh, g_h_h);
    cudaGetSymbolAddress((void**)&interh, g_inter_h);
    cudaGetSymbolAddress((void**)&avgouth, g_avgout_h);
    cudaGetSymbolAddress((void**)&inh, g_in_h);
    cudaGetSymbolAddress((void**)&gatesh, g_gates_h);
    cudaGetSymbolAddress((void**)&w1t, g_w1t);
    cudaGetSymbolAddress((void**)&w2t, g_w2t);
    cudaGetSymbolAddress((void**)&wgt, g_wgt);

    cudaFuncSetAttribute(k_gemm_h<0, DD, DD>,
                         cudaFuncAttributeMaxDynamicSharedMemorySize, GEMM_SMEM);
    cudaFuncSetAttribute(k_gemm_h<1, DD, DD>,
                         cudaFuncAttributeMaxDynamicSharedMemorySize, GEMM_SMEM);
    cudaFuncSetAttribute(k_gemm_h<2, DD2, DD2>,
                         cudaFuncAttributeMaxDynamicSharedMemorySize, GEMM_SMEM);

    dim3 tb(32, 8);
    k_transpose<<<dim3(DD / 32, DD / 32), tb>>>(w1, w1t, DD);
    k_transpose<<<dim3(DD / 32, DD / 32), tb>>>(w2, w2t, DD);
    k_transpose<<<dim3(DD2 / 32, DD2 / 32), tb>>>(wg, wgt, DD2);

    k_chunksum<<<(BB * NCH * (DD / 4)) / 256, 256>>>(inputs);   // 512 blocks
    k_scan<<<(BB * (DD / 4)) / 256, 256>>>();                   // 8 blocks
    k_apply<<<(BB * NCH * (DD / 4)) / 256, 256>>>(inputs);      // 512 blocks
    k_ln<<<MM, 256>>>(lng, lnb);

    dim3 grid12(DD / 128, MM / 128);     // (8, 256)
    k_gemm_h<0, DD, DD><<<grid12, 256, GEMM_SMEM>>>(hh, hh, w1t, b1, nullptr,
                                                    nullptr, interh);
    k_gemm_h<1, DD, DD><<<grid12, 256, GEMM_SMEM>>>(interh, interh, w2t, b2, avg,
                                                    avgout, avgouth);

    dim3 grid3(DD2 / 128, MM / 128);     // (16, 256)
    k_gemm_h<2, DD2, DD2><<<grid3, 256, GEMM_SMEM>>>(inh, avgouth, wgt, bg,
                                                     nullptr, nullptr, gatesh);

    k_final<<<((size_t)MM * DD / 4) / 256, 256>>>(inputs, out);
}

// round 13
// speedup vs baseline: 1.1343x; 1.0223x over previous
#include <cuda_runtime.h>
#include <cuda_fp16.h>
#include <math.h>
#include <stdint.h>
#include <string.h>

#define BB 8
#define LL 4096
#define DD 1024
#define MM (BB * LL)          // 32768 rows
#define DD2 (2 * DD)          // 2048
#define NCH 64
#define CHUNK (LL / NCH)      // 64

// ---------------- scratch (device globals; no allocation allowed) ----------
__device__ float  g_avg[(size_t)MM * DD];      // cumulative mean (fp32)
__device__ __half g_h_h[(size_t)MM * DD];      // layernorm(avg), fp16
__device__ __half g_inter_h[(size_t)MM * DD];  // relu(h@w1+b1), fp16
__device__ __half g_avgout_h[(size_t)MM * DD]; // avgout, fp16
__device__ __half g_in_h[(size_t)MM * DD];     // fp16 inputs
__device__ __half g_gates_h[(size_t)MM * DD2]; // concat@wg+bg, fp16
__device__ float  g_csum[BB * NCH * DD];       // chunk partial sums
__device__ __half g_w1t[DD * DD];              // w1^T [N][K], fp16
__device__ __half g_w2t[DD * DD];
__device__ __half g_wgt[(size_t)DD2 * DD2];

// ---------------- helpers ----------------------------------------------------
__device__ __forceinline__ float sigf(float x) { return 1.f / (1.f + __expf(-x)); }

__device__ __forceinline__ uint32_t h2_bits(__half2 h) {
    uint32_t u;
    memcpy(&u, &h, 4);
    return u;
}

#define CP_ASYNC16(dst, src) \
    asm volatile("cp.async.cg.shared.global [%0], [%1], 16;" \
                 :: "r"(dst), "l"(src) : "memory")
#define CP_COMMIT() asm volatile("cp.async.commit_group;" ::: "memory")

#define MMA_F16(c, a0, a1, a2, a3, b0, b1)                                    \
    asm volatile(                                                             \
        "mma.sync.aligned.m16n8k16.row.col.f32.f16.f16.f32 "                  \
        "{%0,%1,%2,%3}, {%4,%5,%6,%7}, {%8,%9}, {%0,%1,%2,%3};"               \
        : "+f"((c)[0]), "+f"((c)[1]), "+f"((c)[2]), "+f"((c)[3])              \
        : "r"(a0), "r"(a1), "r"(a2), "r"(a3), "r"(b0), "r"(b1))

#define LDSM_X4(r0, r1, r2, r3, addr)                                         \
    asm volatile("ldmatrix.sync.aligned.m8n8.x4.shared.b16 {%0,%1,%2,%3}, [%4];" \
                 : "=r"(r0), "=r"(r1), "=r"(r2), "=r"(r3) : "r"(addr))

// ---------------- phase 1: chunked cumulative sum (float4 vectorized) --------
__global__ void __launch_bounds__(256) k_chunksum(const float* __restrict__ in) {
    int idx = blockIdx.x * blockDim.x + threadIdx.x;   // 131072
    int d4 = idx & 255;
    int chunk = (idx >> 8) & (NCH - 1);
    int b = idx >> 14;
    const float4* p = reinterpret_cast<const float4*>(
        in + ((size_t)(b * LL + chunk * CHUNK)) * DD) + d4;
    float4 s = make_float4(0.f, 0.f, 0.f, 0.f);
#pragma unroll 4
    for (int l = 0; l < CHUNK; ++l) {
        float4 v = p[(size_t)l * 256];
        s.x += v.x; s.y += v.y; s.z += v.z; s.w += v.w;
    }
    reinterpret_cast<float4*>(g_csum + (b * NCH + chunk) * DD)[d4] = s;
}

__global__ void __launch_bounds__(256) k_scan() {
    int idx = blockIdx.x * blockDim.x + threadIdx.x;   // B*D/4 = 2048
    int d4 = idx & 255;
    int b = idx >> 8;
    float4 run = make_float4(0.f, 0.f, 0.f, 0.f);
#pragma unroll
    for (int c = 0; c < NCH; ++c) {
        float4* q = reinterpret_cast<float4*>(g_csum + (b * NCH + c) * DD) + d4;
        float4 t = *q;
        *q = run;                                       // exclusive
        run.x += t.x; run.y += t.y; run.z += t.z; run.w += t.w;
    }
}

__global__ void __launch_bounds__(256) k_apply(const float* __restrict__ in) {
    int idx = blockIdx.x * blockDim.x + threadIdx.x;   // 131072
    int d4 = idx & 255;
    int chunk = (idx >> 8) & (NCH - 1);
    int b = idx >> 14;
    size_t rowbase = (size_t)(b * LL + chunk * CHUNK) * DD;
    const float4* p = reinterpret_cast<const float4*>(in + rowbase) + d4;
    float4* q = reinterpret_cast<float4*>(g_avg + rowbase) + d4;
    uint2* qh = reinterpret_cast<uint2*>(g_in_h + rowbase) + d4;
    float4 run = reinterpret_cast<const float4*>(
        g_csum + (b * NCH + chunk) * DD)[d4];
    int l0 = chunk * CHUNK;
#pragma unroll 4
    for (int l = 0; l < CHUNK; ++l) {
        float4 v = p[(size_t)l * 256];
        run.x += v.x; run.y += v.y; run.z += v.z; run.w += v.w;
        float den = (float)(l0 + l + 1);
        float4 a;
        a.x = run.x / den; a.y = run.y / den;
        a.z = run.z / den; a.w = run.w / den;
        q[(size_t)l * 256] = a;
        uint2 hv;
        hv.x = h2_bits(__floats2half2_rn(v.x, v.y));
        hv.y = h2_bits(__floats2half2_rn(v.z, v.w));
        qh[(size_t)l * 256] = hv;
    }
}

// ---------------- phase 2: layernorm over D per row (fp16 out) ---------------
__global__ void __launch_bounds__(256) k_ln(const float* __restrict__ lng,
                                            const float* __restrict__ lnb) {
    int row = blockIdx.x;
    int t = threadIdx.x;
    const float4* x4 = reinterpret_cast<const float4*>(g_avg + (size_t)row * DD);
    float4 a = x4[t];
    float s = a.x + a.y + a.z + a.w;
    float ss = a.x * a.x + a.y * a.y + a.z * a.z + a.w * a.w;
#pragma unroll
    for (int o = 16; o > 0; o >>= 1) {
        s  += __shfl_xor_sync(0xffffffffu, s, o);
        ss += __shfl_xor_sync(0xffffffffu, ss, o);
    }
    __shared__ float sm[16];
    int w = t >> 5;
    if ((t & 31) == 0) { sm[w] = s; sm[8 + w] = ss; }
    __syncthreads();
    if (t < 32) {
        float v1 = (t < 8) ? sm[t] : 0.f;
        float v2 = (t < 8) ? sm[8 + t] : 0.f;
#pragma unroll
        for (int o = 4; o > 0; o >>= 1) {
            v1 += __shfl_xor_sync(0xffffffffu, v1, o);
            v2 += __shfl_xor_sync(0xffffffffu, v2, o);
        }
        if (t == 0) { sm[0] = v1; sm[1] = v2; }
    }
    __syncthreads();
    float mean = sm[0] * (1.f / DD);
    float var  = sm[1] * (1.f / DD) - mean * mean;
    float inv  = rsqrtf(var + 1e-6f);
    float4 g = reinterpret_cast<const float4*>(lng)[t];
    float4 b = reinterpret_cast<const float4*>(lnb)[t];
    __half2 h0 = __floats2half2_rn((a.x - mean) * inv * g.x + b.x,
                                   (a.y - mean) * inv * g.y + b.y);
    __half2 h1 = __floats2half2_rn((a.z - mean) * inv * g.z + b.z,
                                   (a.w - mean) * inv * g.w + b.w);
    __half2* dst = reinterpret_cast<__half2*>(g_h_h + (size_t)row * DD);
    dst[t * 2 + 0] = h0;
    dst[t * 2 + 1] = h1;
}

// ---------------- weight transpose (fp16 out): Wt[n][k] = W[k][n] ------------
__global__ void __launch_bounds__(256) k_transpose(const float* __restrict__ W,
                                                   __half* __restrict__ Wt, int N) {
    __shared__ float t[32][33];
    int bx = blockIdx.x * 32, by = blockIdx.y * 32;
    int x = bx + threadIdx.x;
#pragma unroll
    for (int i = 0; i < 32; i += 8)
        t[threadIdx.y + i][threadIdx.x] = W[(size_t)(by + threadIdx.y + i) * N + x];
    __syncthreads();
    int x2 = by + threadIdx.x;
#pragma unroll
    for (int i = 0; i < 32; i += 8)
        Wt[(size_t)(bx + threadIdx.y + i) * N + x2] =
            __float2half_rn(t[threadIdx.x][threadIdx.y + i]);
}

// ---------------- phase 3: fp16 mma.sync GEMM (R8 config, proven best) -------
// C[M,NN] = concatA[M,KTOT] @ Wt[NN,KTOT]^T (fp16 operands, fp32 accum).
// CTA tile 128x128, BK=64 halves, 8 warps (2x4), warp tile 64x32, m16n8k16.
// ldmatrix.x4 fragments; 3-stage cp.async pipeline, 1 barrier/iter, 2 CTAs/SM.
// MODE 0: relu(x+b) -> Ch   MODE 1: x+b+add(fp32) -> fp16 Ch   MODE 2: x+b -> Ch
#define LDPH 72
#define TILE_H (128 * LDPH)               // halves per tile
#define STG_H (2 * TILE_H)                // A + B per stage
#define GEMM_SMEM (3 * STG_H * 2)         // 3 stages = 110592 B

template <int MODE, int KTOT, int NN>
__global__ void __launch_bounds__(256, 2) k_gemm_h(
    const __half* __restrict__ A0, const __half* __restrict__ A1,
    const __half* __restrict__ Wt, const float* __restrict__ bias,
    const float* __restrict__ add, __half* __restrict__ Ch) {
    extern __shared__ __half smh[];
    int tid = threadIdx.x;
    int wid = tid >> 5, lane = tid & 31;
    int g = lane >> 2, tg = lane & 3;
    int wm = wid >> 2, wn = wid & 3;       // 2 x 4 warp grid
    int bm = blockIdx.y * 128, bn = blockIdx.x * 128;

    // per-lane ldmatrix offsets (in halves, within tile)
    int la_off = (lane & 15) * LDPH + (lane >> 4) * 8;                 // A x4
    int qb = lane >> 3;
    int lb_off = ((lane & 7) + (qb >> 1) * 8) * LDPH + (qb & 1) * 8;   // B x4

    float acc[16][4];
#pragma unroll
    for (int i = 0; i < 16; ++i)
#pragma unroll
        for (int j = 0; j < 4; ++j) acc[i][j] = 0.f;

    const int NK = KTOT / 64;

#define LOAD_STAGE(s, kk_)                                                     \
    {                                                                          \
        int kk = (kk_);                                                        \
        const __half* Ab = A0; int kloc = kk;                                  \
        if (KTOT > DD && kk >= DD) { Ab = A1; kloc = kk - DD; }                \
        __half* As = smh + (s) * STG_H;                                        \
        __half* Bs = As + TILE_H;                                              \
        _Pragma("unroll")                                                      \
        for (int it = 0; it < 4; ++it) {                                       \
            int i = tid + it * 256;                                            \
            int r = i >> 3, c = (i & 7) << 3;                                  \
            uint32_t da = (uint32_t)__cvta_generic_to_shared(As + r * LDPH + c); \
            CP_ASYNC16(da, Ab + (size_t)(bm + r) * DD + kloc + c);             \
            uint32_t db = (uint32_t)__cvta_generic_to_shared(Bs + r * LDPH + c); \
            CP_ASYNC16(db, Wt + (size_t)(bn + r) * KTOT + kk + c);             \
        }                                                                      \
    }

    LOAD_STAGE(0, 0);
    CP_COMMIT();
    LOAD_STAGE(1, 64);
    CP_COMMIT();

    int cur = 0;
    for (int kt = 0; kt < NK; ++kt) {
        if (kt + 1 < NK) {
            asm volatile("cp.async.wait_group 1;" ::: "memory");
        } else {
            asm volatile("cp.async.wait_group 0;" ::: "memory");
        }
        __syncthreads();
        if (kt + 2 < NK) {
            int nxt = cur + 2; if (nxt >= 3) nxt -= 3;
            LOAD_STAGE(nxt, (kt + 2) * 64);
            CP_COMMIT();
        }

        const __half* As = smh + cur * STG_H;
        const __half* Bs = As + TILE_H;
        uint32_t aB = (uint32_t)__cvta_generic_to_shared(
            As + (size_t)(wm * 64) * LDPH + la_off);
        uint32_t bB = (uint32_t)__cvta_generic_to_shared(
            Bs + (size_t)(wn * 32) * LDPH + lb_off);
#pragma unroll
        for (int kc = 0; kc < 4; ++kc) {
            int kb2 = kc * 32;                       // byte offset of k16 chunk
            uint32_t af[4][4], bf[4][2];
#pragma unroll
            for (int mt = 0; mt < 4; ++mt)
                LDSM_X4(af[mt][0], af[mt][1], af[mt][2], af[mt][3],
                        aB + mt * (16 * LDPH * 2) + kb2);
#pragma unroll
            for (int p = 0; p < 2; ++p)
                LDSM_X4(bf[p * 2][0], bf[p * 2][1], bf[p * 2 + 1][0],
                        bf[p * 2 + 1][1], bB + p * (16 * LDPH * 2) + kb2);
#pragma unroll
            for (int mt = 0; mt < 4; ++mt)
#pragma unroll
                for (int nt = 0; nt < 4; ++nt)
                    MMA_F16(acc[mt * 4 + nt], af[mt][0], af[mt][1], af[mt][2],
                            af[mt][3], bf[nt][0], bf[nt][1]);
        }
        ++cur; if (cur >= 3) cur = 0;
    }

#pragma unroll
    for (int mt = 0; mt < 4; ++mt) {
#pragma unroll
        for (int nt = 0; nt < 4; ++nt) {
            float* c = acc[mt * 4 + nt];
            int col = bn + wn * 32 + nt * 8 + 2 * tg;
            float2 bb = *reinterpret_cast<const float2*>(bias + col);
#pragma unroll
            for (int hh = 0; hh < 2; ++hh) {
                int row = bm + wm * 64 + mt * 16 + g + hh * 8;
                size_t off = (size_t)row * NN + col;
                float vx = c[hh * 2 + 0] + bb.x;
                float vy = c[hh * 2 + 1] + bb.y;
                if (MODE == 0) {
                    *reinterpret_cast<__half2*>(Ch + off) =
                        __floats2half2_rn(fmaxf(vx, 0.f), fmaxf(vy, 0.f));
                } else if (MODE == 1) {
                    float2 ad = *reinterpret_cast<const float2*>(add + off);
                    vx += ad.x; vy += ad.y;
                    *reinterpret_cast<__half2*>(Ch + off) = __floats2half2_rn(vx, vy);
                } else {
                    *reinterpret_cast<__half2*>(Ch + off) = __floats2half2_rn(vx, vy);
                }
            }
        }
    }
#undef LOAD_STAGE
}

// ---------------- phase 4: gate combine (all-fp16 reads) ----------------------
__global__ void __launch_bounds__(256) k_final(float* __restrict__ out) {
    int idx = blockIdx.x * blockDim.x + threadIdx.x;   // over M*D/4
    int row = idx >> 8;                                 // D/4 = 256
    int d4 = idx & 255;
    uint2 ih = reinterpret_cast<const uint2*>(g_in_h)[idx];
    uint2 ah = reinterpret_cast<const uint2*>(g_avgout_h)[idx];
    __half2 i0, i1, a0, a1;
    memcpy(&i0, &ih.x, 4); memcpy(&i1, &ih.y, 4);
    memcpy(&a0, &ah.x, 4); memcpy(&a1, &ah.y, 4);
    const __half2* gr = reinterpret_cast<const __half2*>(
        g_gates_h + (size_t)row * DD2);
    __half2 g1a = gr[d4 * 2 + 0];
    __half2 g1b = gr[d4 * 2 + 1];
    __half2 g2a = gr[512 + d4 * 2 + 0];
    __half2 g2b = gr[512 + d4 * 2 + 1];
    float4 o;
    o.x = sigf(__low2float(g1a))  * __low2float(i0)  + sigf(__low2float(g2a))  * __low2float(a0);
    o.y = sigf(__high2float(g1a)) * __high2float(i0) + sigf(__high2float(g2a)) * __high2float(a0);
    o.z = sigf(__low2float(g1b))  * __low2float(i1)  + sigf(__low2float(g2b))  * __low2float(a1);
    o.w = sigf(__high2float(g1b)) * __high2float(i1) + sigf(__high2float(g2b)) * __high2float(a1);
    reinterpret_cast<float4*>(out)[idx] = o;
}

// ---------------- launch -----------------------------------------------------
extern "C" void kernel_launch(void* const* d_in, const int* in_sizes, int n_in,
                              void* d_out, int out_size) {
    const float* inputs = (const float*)d_in[0];
    const float* w1 = (const float*)d_in[1];
    const float* b1 = (const float*)d_in[2];
    const float* w2 = (const float*)d_in[3];
    const float* b2 = (const float*)d_in[4];
    const float* lng = (const float*)d_in[5];
    const float* lnb = (const float*)d_in[6];
    const float* wg = (const float*)d_in[7];
    const float* bg = (const float*)d_in[8];
    float* out = (float*)d_out;

    float *avg;
    __half *hh, *interh, *avgouth, *inh, *gatesh, *w1t, *w2t, *wgt;
    cudaGetSymbolAddress((void**)&avg, g_avg);
    cudaGetSymbolAddress((void**)&hh, g_h_h);
    cudaGetSymbolAddress((void**)&interh, g_inter_h);
    cudaGetSymbolAddress((void**)&avgouth, g_avgout_h);
    cudaGetSymbolAddress((void**)&inh, g_in_h);
    cudaGetSymbolAddress((void**)&gatesh, g_gates_h);
    cudaGetSymbolAddress((void**)&w1t, g_w1t);
    cudaGetSymbolAddress((void**)&w2t, g_w2t);
    cudaGetSymbolAddress((void**)&wgt, g_wgt);

    cudaFuncSetAttribute(k_gemm_h<0, DD, DD>,
                         cudaFuncAttributeMaxDynamicSharedMemorySize, GEMM_SMEM);
    cudaFuncSetAttribute(k_gemm_h<1, DD, DD>,
                         cudaFuncAttributeMaxDynamicSharedMemorySize, GEMM_SMEM);
    cudaFuncSetAttribute(k_gemm_h<2, DD2, DD2>,
                         cudaFuncAttributeMaxDynamicSharedMemorySize, GEMM_SMEM);

    dim3 tb(32, 8);
    k_transpose<<<dim3(DD / 32, DD / 32), tb>>>(w1, w1t, DD);
    k_transpose<<<dim3(DD / 32, DD / 32), tb>>>(w2, w2t, DD);
    k_transpose<<<dim3(DD2 / 32, DD2 / 32), tb>>>(wg, wgt, DD2);

    k_chunksum<<<(BB * NCH * (DD / 4)) / 256, 256>>>(inputs);   // 512 blocks
    k_scan<<<(BB * (DD / 4)) / 256, 256>>>();                   // 8 blocks
    k_apply<<<(BB * NCH * (DD / 4)) / 256, 256>>>(inputs);      // 512 blocks
    k_ln<<<MM, 256>>>(lng, lnb);

    dim3 grid12(DD / 128, MM / 128);     // (8, 256)
    k_gemm_h<0, DD, DD><<<grid12, 256, GEMM_SMEM>>>(hh, hh, w1t, b1, nullptr,
                                                    interh);
    k_gemm_h<1, DD, DD><<<grid12, 256, GEMM_SMEM>>>(interh, interh, w2t, b2, avg,
                                                    avgouth);

    dim3 grid3(DD2 / 128, MM / 128);     // (16, 256)
    k_gemm_h<2, DD2, DD2><<<grid3, 256, GEMM_SMEM>>>(inh, avgouth, wgt, bg,
                                                     nullptr, gatesh);

    k_final<<<((size_t)MM * DD / 4) / 256, 256>>>(out);
}

// round 14
// speedup vs baseline: 1.1538x; 1.0171x over previous
#include <cuda_runtime.h>
#include <cuda_fp16.h>
#include <math.h>
#include <stdint.h>
#include <string.h>

#define BB 8
#define LL 4096
#define DD 1024
#define MM (BB * LL)          // 32768 rows
#define DD2 (2 * DD)          // 2048
#define NCH 64
#define CHUNK (LL / NCH)      // 64

// ---------------- scratch (device globals; no allocation allowed) ----------
__device__ __half g_avg_h[(size_t)MM * DD];    // cumulative mean, fp16
__device__ __half g_h_h[(size_t)MM * DD];      // layernorm(avg), fp16
__device__ __half g_inter_h[(size_t)MM * DD];  // relu(h@w1+b1), fp16
__device__ __half g_avgout_h[(size_t)MM * DD]; // avgout, fp16
__device__ __half g_in_h[(size_t)MM * DD];     // fp16 inputs
__device__ __half g_gates_h[(size_t)MM * DD2]; // concat@wg+bg, fp16
__device__ float  g_csum[BB * NCH * DD];       // chunk partial sums
__device__ __half g_w1t[DD * DD];              // w1^T [N][K], fp16
__device__ __half g_w2t[DD * DD];
__device__ __half g_wgt[(size_t)DD2 * DD2];

// ---------------- helpers ----------------------------------------------------
__device__ __forceinline__ float sigf(float x) { return 1.f / (1.f + __expf(-x)); }

__device__ __forceinline__ uint32_t h2_bits(__half2 h) {
    uint32_t u;
    memcpy(&u, &h, 4);
    return u;
}
__device__ __forceinline__ __half2 bits_h2(uint32_t u) {
    __half2 h;
    memcpy(&h, &u, 4);
    return h;
}

#define CP_ASYNC16(dst, src) \
    asm volatile("cp.async.cg.shared.global [%0], [%1], 16;" \
                 :: "r"(dst), "l"(src) : "memory")
#define CP_COMMIT() asm volatile("cp.async.commit_group;" ::: "memory")

#define MMA_F16(c, a0, a1, a2, a3, b0, b1)                                    \
    asm volatile(                                                             \
        "mma.sync.aligned.m16n8k16.row.col.f32.f16.f16.f32 "                  \
        "{%0,%1,%2,%3}, {%4,%5,%6,%7}, {%8,%9}, {%0,%1,%2,%3};"               \
        : "+f"((c)[0]), "+f"((c)[1]), "+f"((c)[2]), "+f"((c)[3])              \
        : "r"(a0), "r"(a1), "r"(a2), "r"(a3), "r"(b0), "r"(b1))

#define LDSM_X4(r0, r1, r2, r3, addr)                                         \
    asm volatile("ldmatrix.sync.aligned.m8n8.x4.shared.b16 {%0,%1,%2,%3}, [%4];" \
                 : "=r"(r0), "=r"(r1), "=r"(r2), "=r"(r3) : "r"(addr))

// ---------------- phase 1: chunked cumulative sum (float4 vectorized) --------
__global__ void __launch_bounds__(256) k_chunksum(const float* __restrict__ in) {
    int idx = blockIdx.x * blockDim.x + threadIdx.x;   // 131072
    int d4 = idx & 255;
    int chunk = (idx >> 8) & (NCH - 1);
    int b = idx >> 14;
    const float4* p = reinterpret_cast<const float4*>(
        in + ((size_t)(b * LL + chunk * CHUNK)) * DD) + d4;
    float4 s = make_float4(0.f, 0.f, 0.f, 0.f);
#pragma unroll 4
    for (int l = 0; l < CHUNK; ++l) {
        float4 v = p[(size_t)l * 256];
        s.x += v.x; s.y += v.y; s.z += v.z; s.w += v.w;
    }
    reinterpret_cast<float4*>(g_csum + (b * NCH + chunk) * DD)[d4] = s;
}

__global__ void __launch_bounds__(256) k_scan() {
    int idx = blockIdx.x * blockDim.x + threadIdx.x;   // B*D/4 = 2048
    int d4 = idx & 255;
    int b = idx >> 8;
    float4 run = make_float4(0.f, 0.f, 0.f, 0.f);
#pragma unroll
    for (int c = 0; c < NCH; ++c) {
        float4* q = reinterpret_cast<float4*>(g_csum + (b * NCH + c) * DD) + d4;
        float4 t = *q;
        *q = run;                                       // exclusive
        run.x += t.x; run.y += t.y; run.z += t.z; run.w += t.w;
    }
}

__global__ void __launch_bounds__(256) k_apply(const float* __restrict__ in) {
    int idx = blockIdx.x * blockDim.x + threadIdx.x;   // 131072
    int d4 = idx & 255;
    int chunk = (idx >> 8) & (NCH - 1);
    int b = idx >> 14;
    size_t rowbase = (size_t)(b * LL + chunk * CHUNK) * DD;
    const float4* p = reinterpret_cast<const float4*>(in + rowbase) + d4;
    uint2* qa = reinterpret_cast<uint2*>(g_avg_h + rowbase) + d4;
    uint2* qh = reinterpret_cast<uint2*>(g_in_h + rowbase) + d4;
    float4 run = reinterpret_cast<const float4*>(
        g_csum + (b * NCH + chunk) * DD)[d4];
    int l0 = chunk * CHUNK;
#pragma unroll 4
    for (int l = 0; l < CHUNK; ++l) {
        float4 v = p[(size_t)l * 256];
        run.x += v.x; run.y += v.y; run.z += v.z; run.w += v.w;
        float den = (float)(l0 + l + 1);
        uint2 av;
        av.x = h2_bits(__floats2half2_rn(run.x / den, run.y / den));
        av.y = h2_bits(__floats2half2_rn(run.z / den, run.w / den));
        qa[(size_t)l * 256] = av;
        uint2 hv;
        hv.x = h2_bits(__floats2half2_rn(v.x, v.y));
        hv.y = h2_bits(__floats2half2_rn(v.z, v.w));
        qh[(size_t)l * 256] = hv;
    }
}

// ---------------- phase 2: layernorm over D per row (fp16 in/out) ------------
__global__ void __launch_bounds__(256) k_ln(const float* __restrict__ lng,
                                            const float* __restrict__ lnb) {
    int row = blockIdx.x;
    int t = threadIdx.x;
    uint2 xb = reinterpret_cast<const uint2*>(g_avg_h + (size_t)row * DD)[t];
    __half2 x0 = bits_h2(xb.x), x1 = bits_h2(xb.y);
    float4 a;
    a.x = __low2float(x0); a.y = __high2float(x0);
    a.z = __low2float(x1); a.w = __high2float(x1);
    float s = a.x + a.y + a.z + a.w;
    float ss = a.x * a.x + a.y * a.y + a.z * a.z + a.w * a.w;
#pragma unroll
    for (int o = 16; o > 0; o >>= 1) {
        s  += __shfl_xor_sync(0xffffffffu, s, o);
        ss += __shfl_xor_sync(0xffffffffu, ss, o);
    }
    __shared__ float sm[16];
    int w = t >> 5;
    if ((t & 31) == 0) { sm[w] = s; sm[8 + w] = ss; }
    __syncthreads();
    if (t < 32) {
        float v1 = (t < 8) ? sm[t] : 0.f;
        float v2 = (t < 8) ? sm[8 + t] : 0.f;
#pragma unroll
        for (int o = 4; o > 0; o >>= 1) {
            v1 += __shfl_xor_sync(0xffffffffu, v1, o);
            v2 += __shfl_xor_sync(0xffffffffu, v2, o);
        }
        if (t == 0) { sm[0] = v1; sm[1] = v2; }
    }
    __syncthreads();
    float mean = sm[0] * (1.f / DD);
    float var  = sm[1] * (1.f / DD) - mean * mean;
    float inv  = rsqrtf(var + 1e-6f);
    float4 g = reinterpret_cast<const float4*>(lng)[t];
    float4 b = reinterpret_cast<const float4*>(lnb)[t];
    __half2 h0 = __floats2half2_rn((a.x - mean) * inv * g.x + b.x,
                                   (a.y - mean) * inv * g.y + b.y);
    __half2 h1 = __floats2half2_rn((a.z - mean) * inv * g.z + b.z,
                                   (a.w - mean) * inv * g.w + b.w);
    __half2* dst = reinterpret_cast<__half2*>(g_h_h + (size_t)row * DD);
    dst[t * 2 + 0] = h0;
    dst[t * 2 + 1] = h1;
}

// ---------------- weight transpose (fp16 out): Wt[n][k] = W[k][n] ------------
__global__ void __launch_bounds__(256) k_transpose(const float* __restrict__ W,
                                                   __half* __restrict__ Wt, int N) {
    __shared__ float t[32][33];
    int bx = blockIdx.x * 32, by = blockIdx.y * 32;
    int x = bx + threadIdx.x;
#pragma unroll
    for (int i = 0; i < 32; i += 8)
        t[threadIdx.y + i][threadIdx.x] = W[(size_t)(by + threadIdx.y + i) * N + x];
    __syncthreads();
    int x2 = by + threadIdx.x;
#pragma unroll
    for (int i = 0; i < 32; i += 8)
        Wt[(size_t)(bx + threadIdx.y + i) * N + x2] =
            __float2half_rn(t[threadIdx.x][threadIdx.y + i]);
}

// ---------------- phase 3: fp16 mma.sync GEMM (R8 config, proven best) -------
// C[M,NN] = concatA[M,KTOT] @ Wt[NN,KTOT]^T (fp16 operands, fp32 accum).
// CTA tile 128x128, BK=64 halves, 8 warps (2x4), warp tile 64x32, m16n8k16.
// ldmatrix.x4 fragments; 3-stage cp.async pipeline, 1 barrier/iter, 2 CTAs/SM.
// MODE 0: relu(x+b) -> Ch   MODE 1: x+b+add(fp16) -> Ch   MODE 2: x+b -> Ch
#define LDPH 72
#define TILE_H (128 * LDPH)               // halves per tile
#define STG_H (2 * TILE_H)                // A + B per stage
#define GEMM_SMEM (3 * STG_H * 2)         // 3 stages = 110592 B

template <int MODE, int KTOT, int NN>
__global__ void __launch_bounds__(256, 2) k_gemm_h(
    const __half* __restrict__ A0, const __half* __restrict__ A1,
    const __half* __restrict__ Wt, const float* __restrict__ bias,
    const __half* __restrict__ add, __half* __restrict__ Ch) {
    extern __shared__ __half smh[];
    int tid = threadIdx.x;
    int wid = tid >> 5, lane = tid & 31;
    int g = lane >> 2, tg = lane & 3;
    int wm = wid >> 2, wn = wid & 3;       // 2 x 4 warp grid
    int bm = blockIdx.y * 128, bn = blockIdx.x * 128;

    // per-lane ldmatrix offsets (in halves, within tile)
    int la_off = (lane & 15) * LDPH + (lane >> 4) * 8;                 // A x4
    int qb = lane >> 3;
    int lb_off = ((lane & 7) + (qb >> 1) * 8) * LDPH + (qb & 1) * 8;   // B x4

    float acc[16][4];
#pragma unroll
    for (int i = 0; i < 16; ++i)
#pragma unroll
        for (int j = 0; j < 4; ++j) acc[i][j] = 0.f;

    const int NK = KTOT / 64;

#define LOAD_STAGE(s, kk_)                                                     \
    {                                                                          \
        int kk = (kk_);                                                        \
        const __half* Ab = A0; int kloc = kk;                                  \
        if (KTOT > DD && kk >= DD) { Ab = A1; kloc = kk - DD; }                \
        __half* As = smh + (s) * STG_H;                                        \
        __half* Bs = As + TILE_H;                                              \
        _Pragma("unroll")                                                      \
        for (int it = 0; it < 4; ++it) {                                       \
            int i = tid + it * 256;                                            \
            int r = i >> 3, c = (i & 7) << 3;                                  \
            uint32_t da = (uint32_t)__cvta_generic_to_shared(As + r * LDPH + c); \
            CP_ASYNC16(da, Ab + (size_t)(bm + r) * DD + kloc + c);             \
            uint32_t db = (uint32_t)__cvta_generic_to_shared(Bs + r * LDPH + c); \
            CP_ASYNC16(db, Wt + (size_t)(bn + r) * KTOT + kk + c);             \
        }                                                                      \
    }

    LOAD_STAGE(0, 0);
    CP_COMMIT();
    LOAD_STAGE(1, 64);
    CP_COMMIT();

    int cur = 0;
    for (int kt = 0; kt < NK; ++kt) {
        if (kt + 1 < NK) {
            asm volatile("cp.async.wait_group 1;" ::: "memory");
        } else {
            asm volatile("cp.async.wait_group 0;" ::: "memory");
        }
        __syncthreads();
        if (kt + 2 < NK) {
            int nxt = cur + 2; if (nxt >= 3) nxt -= 3;
            LOAD_STAGE(nxt, (kt + 2) * 64);
            CP_COMMIT();
        }

        const __half* As = smh + cur * STG_H;
        const __half* Bs = As + TILE_H;
        uint32_t aB = (uint32_t)__cvta_generic_to_shared(
            As + (size_t)(wm * 64) * LDPH + la_off);
        uint32_t bB = (uint32_t)__cvta_generic_to_shared(
            Bs + (size_t)(wn * 32) * LDPH + lb_off);
#pragma unroll
        for (int kc = 0; kc < 4; ++kc) {
            int kb2 = kc * 32;                       // byte offset of k16 chunk
            uint32_t af[4][4], bf[4][2];
#pragma unroll
            for (int mt = 0; mt < 4; ++mt)
                LDSM_X4(af[mt][0], af[mt][1], af[mt][2], af[mt][3],
                        aB + mt * (16 * LDPH * 2) + kb2);
#pragma unroll
            for (int p = 0; p < 2; ++p)
                LDSM_X4(bf[p * 2][0], bf[p * 2][1], bf[p * 2 + 1][0],
                        bf[p * 2 + 1][1], bB + p * (16 * LDPH * 2) + kb2);
#pragma unroll
            for (int mt = 0; mt < 4; ++mt)
#pragma unroll
                for (int nt = 0; nt < 4; ++nt)
                    MMA_F16(acc[mt * 4 + nt], af[mt][0], af[mt][1], af[mt][2],
                            af[mt][3], bf[nt][0], bf[nt][1]);
        }
        ++cur; if (cur >= 3) cur = 0;
    }

#pragma unroll
    for (int mt = 0; mt < 4; ++mt) {
#pragma unroll
        for (int nt = 0; nt < 4; ++nt) {
            float* c = acc[mt * 4 + nt];
            int col = bn + wn * 32 + nt * 8 + 2 * tg;
            float2 bb = *reinterpret_cast<const float2*>(bias + col);
#pragma unroll
            for (int hh = 0; hh < 2; ++hh) {
                int row = bm + wm * 64 + mt * 16 + g + hh * 8;
                size_t off = (size_t)row * NN + col;
                float vx = c[hh * 2 + 0] + bb.x;
                float vy = c[hh * 2 + 1] + bb.y;
                if (MODE == 0) {
                    *reinterpret_cast<__half2*>(Ch + off) =
                        __floats2half2_rn(fmaxf(vx, 0.f), fmaxf(vy, 0.f));
                } else if (MODE == 1) {
                    __half2 ad = *reinterpret_cast<const __half2*>(add + off);
                    vx += __low2float(ad);
                    vy += __high2float(ad);
                    *reinterpret_cast<__half2*>(Ch + off) = __floats2half2_rn(vx, vy);
                } else {
                    *reinterpret_cast<__half2*>(Ch + off) = __floats2half2_rn(vx, vy);
                }
            }
        }
    }
#undef LOAD_STAGE
}

// ---------------- phase 4: gate combine (all-fp16 reads) ----------------------
__global__ void __launch_bounds__(256) k_final(float* __restrict__ out) {
    int idx = blockIdx.x * blockDim.x + threadIdx.x;   // over M*D/4
    int row = idx >> 8;                                 // D/4 = 256
    int d4 = idx & 255;
    uint2 ih = reinterpret_cast<const uint2*>(g_in_h)[idx];
    uint2 ah = reinterpret_cast<const uint2*>(g_avgout_h)[idx];
    __half2 i0 = bits_h2(ih.x), i1 = bits_h2(ih.y);
    __half2 a0 = bits_h2(ah.x), a1 = bits_h2(ah.y);
    const __half2* gr = reinterpret_cast<const __half2*>(
        g_gates_h + (size_t)row * DD2);
    __half2 g1a = gr[d4 * 2 + 0];
    __half2 g1b = gr[d4 * 2 + 1];
    __half2 g2a = gr[512 + d4 * 2 + 0];
    __half2 g2b = gr[512 + d4 * 2 + 1];
    float4 o;
    o.x = sigf(__low2float(g1a))  * __low2float(i0)  + sigf(__low2float(g2a))  * __low2float(a0);
    o.y = sigf(__high2float(g1a)) * __high2float(i0) + sigf(__high2float(g2a)) * __high2float(a0);
    o.z = sigf(__low2float(g1b))  * __low2float(i1)  + sigf(__low2float(g2b))  * __low2float(a1);
    o.w = sigf(__high2float(g1b)) * __high2float(i1) + sigf(__high2float(g2b)) * __high2float(a1);
    reinterpret_cast<float4*>(out)[idx] = o;
}

// ---------------- launch -----------------------------------------------------
extern "C" void kernel_launch(void* const* d_in, const int* in_sizes, int n_in,
                              void* d_out, int out_size) {
    const float* inputs = (const float*)d_in[0];
    const float* w1 = (const float*)d_in[1];
    const float* b1 = (const float*)d_in[2];
    const float* w2 = (const float*)d_in[3];
    const float* b2 = (const float*)d_in[4];
    const float* lng = (const float*)d_in[5];
    const float* lnb = (const float*)d_in[6];
    const float* wg = (const float*)d_in[7];
    const float* bg = (const float*)d_in[8];
    float* out = (float*)d_out;

    __half *avgh, *hh, *interh, *avgouth, *inh, *gatesh, *w1t, *w2t, *wgt;
    cudaGetSymbolAddress((void**)&avgh, g_avg_h);
    cudaGetSymbolAddress((void**)&hh, g_h_h);
    cudaGetSymbolAddress((void**)&interh, g_inter_h);
    cudaGetSymbolAddress((void**)&avgouth, g_avgout_h);
    cudaGetSymbolAddress((void**)&inh, g_in_h);
    cudaGetSymbolAddress((void**)&gatesh, g_gates_h);
    cudaGetSymbolAddress((void**)&w1t, g_w1t);
    cudaGetSymbolAddress((void**)&w2t, g_w2t);
    cudaGetSymbolAddress((void**)&wgt, g_wgt);

    cudaFuncSetAttribute(k_gemm_h<0, DD, DD>,
                         cudaFuncAttributeMaxDynamicSharedMemorySize, GEMM_SMEM);
    cudaFuncSetAttribute(k_gemm_h<1, DD, DD>,
                         cudaFuncAttributeMaxDynamicSharedMemorySize, GEMM_SMEM);
    cudaFuncSetAttribute(k_gemm_h<2, DD2, DD2>,
                         cudaFuncAttributeMaxDynamicSharedMemorySize, GEMM_SMEM);

    dim3 tb(32, 8);
    k_transpose<<<dim3(DD / 32, DD / 32), tb>>>(w1, w1t, DD);
    k_transpose<<<dim3(DD / 32, DD / 32), tb>>>(w2, w2t, DD);
    k_transpose<<<dim3(DD2 / 32, DD2 / 32), tb>>>(wg, wgt, DD2);

    k_chunksum<<<(BB * NCH * (DD / 4)) / 256, 256>>>(inputs);   // 512 blocks
    k_scan<<<(BB * (DD / 4)) / 256, 256>>>();                   // 8 blocks
    k_apply<<<(BB * NCH * (DD / 4)) / 256, 256>>>(inputs);      // 512 blocks
    k_ln<<<MM, 256>>>(lng, lnb);

    dim3 grid12(DD / 128, MM / 128);     // (8, 256)
    k_gemm_h<0, DD, DD><<<grid12, 256, GEMM_SMEM>>>(hh, hh, w1t, b1, nullptr,
                                                    interh);
    k_gemm_h<1, DD, DD><<<grid12, 256, GEMM_SMEM>>>(interh, interh, w2t, b2, avgh,
                                                    avgouth);

    dim3 grid3(DD2 / 128, MM / 128);     // (16, 256)
    k_gemm_h<2, DD2, DD2><<<grid3, 256, GEMM_SMEM>>>(inh, avgouth, wgt, bg,
                                                     nullptr, gatesh);

    k_final<<<((size_t)MM * DD / 4) / 256, 256>>>(out);
}

// round 15
// speedup vs baseline: 1.1689x; 1.0131x over previous
#include <cuda_runtime.h>
#include <cuda_fp16.h>
#include <math.h>
#include <stdint.h>
#include <string.h>

#define BB 8
#define LL 4096
#define DD 1024
#define MM (BB * LL)          // 32768 rows
#define DD2 (2 * DD)          // 2048
#define NCH 64
#define CHUNK (LL / NCH)      // 64

// ---------------- scratch (device globals; no allocation allowed) ----------
__device__ __half g_avg_h[(size_t)MM * DD];    // cumulative mean, fp16
__device__ __half g_h_h[(size_t)MM * DD];      // layernorm(avg), fp16
__device__ __half g_inter_h[(size_t)MM * DD];  // relu(h@w1+b1), fp16
__device__ __half g_avgout_h[(size_t)MM * DD]; // avgout, fp16
__device__ __half g_in_h[(size_t)MM * DD];     // fp16 inputs
__device__ __half g_gates_h[(size_t)MM * DD2]; // concat@wg+bg, fp16
__device__ float  g_csum[BB * NCH * DD];       // chunk partial sums
__device__ __half g_w1t[DD * DD];              // w1^T [N][K], fp16
__device__ __half g_w2t[DD * DD];
__device__ __half g_wgt[(size_t)DD2 * DD2];

// ---------------- helpers ----------------------------------------------------
__device__ __forceinline__ float sigf(float x) { return 1.f / (1.f + __expf(-x)); }

__device__ __forceinline__ uint32_t h2_bits(__half2 h) {
    uint32_t u;
    memcpy(&u, &h, 4);
    return u;
}
__device__ __forceinline__ __half2 bits_h2(uint32_t u) {
    __half2 h;
    memcpy(&h, &u, 4);
    return h;
}

#define CP_ASYNC16(dst, src) \
    asm volatile("cp.async.cg.shared.global [%0], [%1], 16;" \
                 :: "r"(dst), "l"(src) : "memory")
#define CP_COMMIT() asm volatile("cp.async.commit_group;" ::: "memory")

#define MMA_F16(c, a0, a1, a2, a3, b0, b1)                                    \
    asm volatile(                                                             \
        "mma.sync.aligned.m16n8k16.row.col.f32.f16.f16.f32 "                  \
        "{%0,%1,%2,%3}, {%4,%5,%6,%7}, {%8,%9}, {%0,%1,%2,%3};"               \
        : "+f"((c)[0]), "+f"((c)[1]), "+f"((c)[2]), "+f"((c)[3])              \
        : "r"(a0), "r"(a1), "r"(a2), "r"(a3), "r"(b0), "r"(b1))

#define LDSM_X4(r0, r1, r2, r3, addr)                                         \
    asm volatile("ldmatrix.sync.aligned.m8n8.x4.shared.b16 {%0,%1,%2,%3}, [%4];" \
                 : "=r"(r0), "=r"(r1), "=r"(r2), "=r"(r3) : "r"(addr))

// ---------------- phase 1a: chunk sums + fp16 input copy ---------------------
__global__ void __launch_bounds__(256) k_chunksum(const float* __restrict__ in) {
    int idx = blockIdx.x * blockDim.x + threadIdx.x;   // 131072
    int d4 = idx & 255;
    int chunk = (idx >> 8) & (NCH - 1);
    int b = idx >> 14;
    size_t base = (size_t)(b * LL + chunk * CHUNK) * DD;
    const float4* p = reinterpret_cast<const float4*>(in + base) + d4;
    uint2* qh = reinterpret_cast<uint2*>(g_in_h + base) + d4;
    float4 s = make_float4(0.f, 0.f, 0.f, 0.f);
#pragma unroll 4
    for (int l = 0; l < CHUNK; ++l) {
        float4 v = p[(size_t)l * 256];
        s.x += v.x; s.y += v.y; s.z += v.z; s.w += v.w;
        uint2 hv;
        hv.x = h2_bits(__floats2half2_rn(v.x, v.y));
        hv.y = h2_bits(__floats2half2_rn(v.z, v.w));
        qh[(size_t)l * 256] = hv;
    }
    reinterpret_cast<float4*>(g_csum + (b * NCH + chunk) * DD)[d4] = s;
}

__global__ void __launch_bounds__(256) k_scan() {
    int idx = blockIdx.x * blockDim.x + threadIdx.x;   // B*D/4 = 2048
    int d4 = idx & 255;
    int b = idx >> 8;
    float4 run = make_float4(0.f, 0.f, 0.f, 0.f);
#pragma unroll
    for (int c = 0; c < NCH; ++c) {
        float4* q = reinterpret_cast<float4*>(g_csum + (b * NCH + c) * DD) + d4;
        float4 t = *q;
        *q = run;                                       // exclusive
        run.x += t.x; run.y += t.y; run.z += t.z; run.w += t.w;
    }
}

// ---------------- phase 1b+2: apply cumsum/mean + fused layernorm ------------
// One block per (b, chunk): 256 threads hold the full D=1024 row per l
// (thread t owns d[4t..4t+3]). Reads fp16 in_h, writes fp16 avg_h and the
// layernorm output h_h (LN computed from the fp32 running average).
__global__ void __launch_bounds__(256) k_apply_ln(const float* __restrict__ lng,
                                                  const float* __restrict__ lnb) {
    int t = threadIdx.x;
    int chunk = blockIdx.x & (NCH - 1);
    int b = blockIdx.x >> 6;
    size_t rowbase = (size_t)(b * LL + chunk * CHUNK) * DD;
    const uint2* pin = reinterpret_cast<const uint2*>(g_in_h + rowbase) + t;
    uint2* qa = reinterpret_cast<uint2*>(g_avg_h + rowbase) + t;
    uint2* qh = reinterpret_cast<uint2*>(g_h_h + rowbase) + t;
    float4 run = reinterpret_cast<const float4*>(
        g_csum + (b * NCH + chunk) * DD)[t];
    float4 gv = reinterpret_cast<const float4*>(lng)[t];
    float4 bv = reinterpret_cast<const float4*>(lnb)[t];
    int l0 = chunk * CHUNK;
    int w = t >> 5;
    __shared__ float sm[2][16];

    for (int l = 0; l < CHUNK; ++l) {
        uint2 iv = pin[(size_t)l * 256];
        __half2 v0 = bits_h2(iv.x), v1 = bits_h2(iv.y);
        run.x += __low2float(v0);  run.y += __high2float(v0);
        run.z += __low2float(v1);  run.w += __high2float(v1);
        float den = 1.f / (float)(l0 + l + 1);
        float4 a;
        a.x = run.x * den; a.y = run.y * den;
        a.z = run.z * den; a.w = run.w * den;
        uint2 av;
        av.x = h2_bits(__floats2half2_rn(a.x, a.y));
        av.y = h2_bits(__floats2half2_rn(a.z, a.w));
        qa[(size_t)l * 256] = av;

        // block reduction for LN (double-buffered smem slot per parity)
        float* smb = sm[l & 1];
        float s = a.x + a.y + a.z + a.w;
        float ss = a.x * a.x + a.y * a.y + a.z * a.z + a.w * a.w;
#pragma unroll
        for (int o = 16; o > 0; o >>= 1) {
            s  += __shfl_xor_sync(0xffffffffu, s, o);
            ss += __shfl_xor_sync(0xffffffffu, ss, o);
        }
        if ((t & 31) == 0) { smb[w] = s; smb[8 + w] = ss; }
        __syncthreads();
        if (t < 32) {
            float v1r = (t < 8) ? smb[t] : 0.f;
            float v2r = (t < 8) ? smb[8 + t] : 0.f;
#pragma unroll
            for (int o = 4; o > 0; o >>= 1) {
                v1r += __shfl_xor_sync(0xffffffffu, v1r, o);
                v2r += __shfl_xor_sync(0xffffffffu, v2r, o);
            }
            if (t == 0) { smb[0] = v1r; smb[1] = v2r; }
        }
        __syncthreads();
        float mean = smb[0] * (1.f / DD);
        float var  = smb[1] * (1.f / DD) - mean * mean;
        float inv  = rsqrtf(var + 1e-6f);
        uint2 hv;
        hv.x = h2_bits(__floats2half2_rn((a.x - mean) * inv * gv.x + bv.x,
                                         (a.y - mean) * inv * gv.y + bv.y));
        hv.y = h2_bits(__floats2half2_rn((a.z - mean) * inv * gv.z + bv.z,
                                         (a.w - mean) * inv * gv.w + bv.w));
        qh[(size_t)l * 256] = hv;
    }
}

// ---------------- weight transpose (fp16 out): Wt[n][k] = W[k][n] ------------
__global__ void __launch_bounds__(256) k_transpose(const float* __restrict__ W,
                                                   __half* __restrict__ Wt, int N) {
    __shared__ float t[32][33];
    int bx = blockIdx.x * 32, by = blockIdx.y * 32;
    int x = bx + threadIdx.x;
#pragma unroll
    for (int i = 0; i < 32; i += 8)
        t[threadIdx.y + i][threadIdx.x] = W[(size_t)(by + threadIdx.y + i) * N + x];
    __syncthreads();
    int x2 = by + threadIdx.x;
#pragma unroll
    for (int i = 0; i < 32; i += 8)
        Wt[(size_t)(bx + threadIdx.y + i) * N + x2] =
            __float2half_rn(t[threadIdx.x][threadIdx.y + i]);
}

// ---------------- phase 3: fp16 mma.sync GEMM (R8 config, proven best) -------
// C[M,NN] = concatA[M,KTOT] @ Wt[NN,KTOT]^T (fp16 operands, fp32 accum).
// CTA tile 128x128, BK=64 halves, 8 warps (2x4), warp tile 64x32, m16n8k16.
// ldmatrix.x4 fragments; 3-stage cp.async pipeline, 1 barrier/iter, 2 CTAs/SM.
// MODE 0: relu(x+b) -> Ch   MODE 1: x+b+add(fp16) -> Ch   MODE 2: x+b -> Ch
#define LDPH 72
#define TILE_H (128 * LDPH)               // halves per tile
#define STG_H (2 * TILE_H)                // A + B per stage
#define GEMM_SMEM (3 * STG_H * 2)         // 3 stages = 110592 B

template <int MODE, int KTOT, int NN>
__global__ void __launch_bounds__(256, 2) k_gemm_h(
    const __half* __restrict__ A0, const __half* __restrict__ A1,
    const __half* __restrict__ Wt, const float* __restrict__ bias,
    const __half* __restrict__ add, __half* __restrict__ Ch) {
    extern __shared__ __half smh[];
    int tid = threadIdx.x;
    int wid = tid >> 5, lane = tid & 31;
    int g = lane >> 2, tg = lane & 3;
    int wm = wid >> 2, wn = wid & 3;       // 2 x 4 warp grid
    int bm = blockIdx.y * 128, bn = blockIdx.x * 128;

    // per-lane ldmatrix offsets (in halves, within tile)
    int la_off = (lane & 15) * LDPH + (lane >> 4) * 8;                 // A x4
    int qb = lane >> 3;
    int lb_off = ((lane & 7) + (qb >> 1) * 8) * LDPH + (qb & 1) * 8;   // B x4

    float acc[16][4];
#pragma unroll
    for (int i = 0; i < 16; ++i)
#pragma unroll
        for (int j = 0; j < 4; ++j) acc[i][j] = 0.f;

    const int NK = KTOT / 64;

#define LOAD_STAGE(s, kk_)                                                     \
    {                                                                          \
        int kk = (kk_);                                                        \
        const __half* Ab = A0; int kloc = kk;                                  \
        if (KTOT > DD && kk >= DD) { Ab = A1; kloc = kk - DD; }                \
        __half* As = smh + (s) * STG_H;                                        \
        __half* Bs = As + TILE_H;                                              \
        _Pragma("unroll")                                                      \
        for (int it = 0; it < 4; ++it) {                                       \
            int i = tid + it * 256;                                            \
            int r = i >> 3, c = (i & 7) << 3;                                  \
            uint32_t da = (uint32_t)__cvta_generic_to_shared(As + r * LDPH + c); \
            CP_ASYNC16(da, Ab + (size_t)(bm + r) * DD + kloc + c);             \
            uint32_t db = (uint32_t)__cvta_generic_to_shared(Bs + r * LDPH + c); \
            CP_ASYNC16(db, Wt + (size_t)(bn + r) * KTOT + kk + c);             \
        }                                                                      \
    }

    LOAD_STAGE(0, 0);
    CP_COMMIT();
    LOAD_STAGE(1, 64);
    CP_COMMIT();

    int cur = 0;
    for (int kt = 0; kt < NK; ++kt) {
        if (kt + 1 < NK) {
            asm volatile("cp.async.wait_group 1;" ::: "memory");
        } else {
            asm volatile("cp.async.wait_group 0;" ::: "memory");
        }
        __syncthreads();
        if (kt + 2 < NK) {
            int nxt = cur + 2; if (nxt >= 3) nxt -= 3;
            LOAD_STAGE(nxt, (kt + 2) * 64);
            CP_COMMIT();
        }

        const __half* As = smh + cur * STG_H;
        const __half* Bs = As + TILE_H;
        uint32_t aB = (uint32_t)__cvta_generic_to_shared(
            As + (size_t)(wm * 64) * LDPH + la_off);
        uint32_t bB = (uint32_t)__cvta_generic_to_shared(
            Bs + (size_t)(wn * 32) * LDPH + lb_off);
#pragma unroll
        for (int kc = 0; kc < 4; ++kc) {
            int kb2 = kc * 32;                       // byte offset of k16 chunk
            uint32_t af[4][4], bf[4][2];
#pragma unroll
            for (int mt = 0; mt < 4; ++mt)
                LDSM_X4(af[mt][0], af[mt][1], af[mt][2], af[mt][3],
                        aB + mt * (16 * LDPH * 2) + kb2);
#pragma unroll
            for (int p = 0; p < 2; ++p)
                LDSM_X4(bf[p * 2][0], bf[p * 2][1], bf[p * 2 + 1][0],
                        bf[p * 2 + 1][1], bB + p * (16 * LDPH * 2) + kb2);
#pragma unroll
            for (int mt = 0; mt < 4; ++mt)
#pragma unroll
                for (int nt = 0; nt < 4; ++nt)
                    MMA_F16(acc[mt * 4 + nt], af[mt][0], af[mt][1], af[mt][2],
                            af[mt][3], bf[nt][0], bf[nt][1]);
        }
        ++cur; if (cur >= 3) cur = 0;
    }

#pragma unroll
    for (int mt = 0; mt < 4; ++mt) {
#pragma unroll
        for (int nt = 0; nt < 4; ++nt) {
            float* c = acc[mt * 4 + nt];
            int col = bn + wn * 32 + nt * 8 + 2 * tg;
            float2 bb = *reinterpret_cast<const float2*>(bias + col);
#pragma unroll
            for (int hh = 0; hh < 2; ++hh) {
                int row = bm + wm * 64 + mt * 16 + g + hh * 8;
                size_t off = (size_t)row * NN + col;
                float vx = c[hh * 2 + 0] + bb.x;
                float vy = c[hh * 2 + 1] + bb.y;
                if (MODE == 0) {
                    *reinterpret_cast<__half2*>(Ch + off) =
                        __floats2half2_rn(fmaxf(vx, 0.f), fmaxf(vy, 0.f));
                } else if (MODE == 1) {
                    __half2 ad = *reinterpret_cast<const __half2*>(add + off);
                    vx += __low2float(ad);
                    vy += __high2float(ad);
                    *reinterpret_cast<__half2*>(Ch + off) = __floats2half2_rn(vx, vy);
                } else {
                    *reinterpret_cast<__half2*>(Ch + off) = __floats2half2_rn(vx, vy);
                }
            }
        }
    }
#undef LOAD_STAGE
}

// ---------------- phase 4: gate combine (all-fp16 reads) ----------------------
__global__ void __launch_bounds__(256) k_final(float* __restrict__ out) {
    int idx = blockIdx.x * blockDim.x + threadIdx.x;   // over M*D/4
    int row = idx >> 8;                                 // D/4 = 256
    int d4 = idx & 255;
    uint2 ih = reinterpret_cast<const uint2*>(g_in_h)[idx];
    uint2 ah = reinterpret_cast<const uint2*>(g_avgout_h)[idx];
    __half2 i0 = bits_h2(ih.x), i1 = bits_h2(ih.y);
    __half2 a0 = bits_h2(ah.x), a1 = bits_h2(ah.y);
    const __half2* gr = reinterpret_cast<const __half2*>(
        g_gates_h + (size_t)row * DD2);
    __half2 g1a = gr[d4 * 2 + 0];
    __half2 g1b = gr[d4 * 2 + 1];
    __half2 g2a = gr[512 + d4 * 2 + 0];
    __half2 g2b = gr[512 + d4 * 2 + 1];
    float4 o;
    o.x = sigf(__low2float(g1a))  * __low2float(i0)  + sigf(__low2float(g2a))  * __low2float(a0);
    o.y = sigf(__high2float(g1a)) * __high2float(i0) + sigf(__high2float(g2a)) * __high2float(a0);
    o.z = sigf(__low2float(g1b))  * __low2float(i1)  + sigf(__low2float(g2b))  * __low2float(a1);
    o.w = sigf(__high2float(g1b)) * __high2float(i1) + sigf(__high2float(g2b)) * __high2float(a1);
    reinterpret_cast<float4*>(out)[idx] = o;
}

// ---------------- launch -----------------------------------------------------
extern "C" void kernel_launch(void* const* d_in, const int* in_sizes, int n_in,
                              void* d_out, int out_size) {
    const float* inputs = (const float*)d_in[0];
    const float* w1 = (const float*)d_in[1];
    const float* b1 = (const float*)d_in[2];
    const float* w2 = (const float*)d_in[3];
    const float* b2 = (const float*)d_in[4];
    const float* lng = (const float*)d_in[5];
    const float* lnb = (const float*)d_in[6];
    const float* wg = (const float*)d_in[7];
    const float* bg = (const float*)d_in[8];
    float* out = (float*)d_out;

    __half *avgh, *hh, *interh, *avgouth, *inh, *gatesh, *w1t, *w2t, *wgt;
    cudaGetSymbolAddress((void**)&avgh, g_avg_h);
    cudaGetSymbolAddress((void**)&hh, g_h_h);
    cudaGetSymbolAddress((void**)&interh, g_inter_h);
    cudaGetSymbolAddress((void**)&avgouth, g_avgout_h);
    cudaGetSymbolAddress((void**)&inh, g_in_h);
    cudaGetSymbolAddress((void**)&gatesh, g_gates_h);
    cudaGetSymbolAddress((void**)&w1t, g_w1t);
    cudaGetSymbolAddress((void**)&w2t, g_w2t);
    cudaGetSymbolAddress((void**)&wgt, g_wgt);

    cudaFuncSetAttribute(k_gemm_h<0, DD, DD>,
                         cudaFuncAttributeMaxDynamicSharedMemorySize, GEMM_SMEM);
    cudaFuncSetAttribute(k_gemm_h<1, DD, DD>,
                         cudaFuncAttributeMaxDynamicSharedMemorySize, GEMM_SMEM);
    cudaFuncSetAttribute(k_gemm_h<2, DD2, DD2>,
                         cudaFuncAttributeMaxDynamicSharedMemorySize, GEMM_SMEM);

    dim3 tb(32, 8);
    k_transpose<<<dim3(DD / 32, DD / 32), tb>>>(w1, w1t, DD);
    k_transpose<<<dim3(DD / 32, DD / 32), tb>>>(w2, w2t, DD);
    k_transpose<<<dim3(DD2 / 32, DD2 / 32), tb>>>(wg, wgt, DD2);

    k_chunksum<<<(BB * NCH * (DD / 4)) / 256, 256>>>(inputs);   // 512 blocks
    k_scan<<<(BB * (DD / 4)) / 256, 256>>>();                   // 8 blocks
    k_apply_ln<<<BB * NCH, 256>>>(lng, lnb);                    // 512 blocks

    dim3 grid12(DD / 128, MM / 128);     // (8, 256)
    k_gemm_h<0, DD, DD><<<grid12, 256, GEMM_SMEM>>>(hh, hh, w1t, b1, nullptr,
                                                    interh);
    k_gemm_h<1, DD, DD><<<grid12, 256, GEMM_SMEM>>>(interh, interh, w2t, b2, avgh,
                                                    avgouth);

    dim3 grid3(DD2 / 128, MM / 128);     // (16, 256)
    k_gemm_h<2, DD2, DD2><<<grid3, 256, GEMM_SMEM>>>(inh, avgouth, wgt, bg,
                                                     nullptr, gatesh);

    k_final<<<((size_t)MM * DD / 4) / 256, 256>>>(out);
}